// round 14
// baseline (speedup 1.0000x reference)
#include <cuda_runtime.h>
#include <cuda_bf16.h>
#include <math.h>

// LRML memory-network scoring — two-kernel pipeline.
//  K1: gather + renormalize rows into a dense __device__ scratch (8192 warps,
//      pure latency-tolerance kernel; all random DRAM traffic lives here).
//  K2: G=4 lanes/element compute on dense, L2-resident data (2048 warps,
//      no ids, no norms — shorter stream, shallow stalls).
//
//  0: user_ids  int32  [B]
//  1: item_ids  int32  [B]
//  2: user_emb  f32    [U, 32]
//  3: item_emb  f32    [I, 32]
//  4: W_att     f32    [10, 32]
//  5: memory    f32    [10, 32]
// Output: f32 [B] = -sum((ue + rel - ie)^2)

#define M 10
#define MAXB 16384

typedef unsigned long long u64t;

__device__ __forceinline__ u64t fma2(u64t a, u64t b, u64t c) {
    u64t d;
    asm("fma.rn.f32x2 %0, %1, %2, %3;" : "=l"(d) : "l"(a), "l"(b), "l"(c));
    return d;
}
__device__ __forceinline__ u64t mul2(u64t a, u64t b) {
    u64t d;
    asm("mul.rn.f32x2 %0, %1, %2;" : "=l"(d) : "l"(a), "l"(b));
    return d;
}
__device__ __forceinline__ u64t pack2(float lo, float hi) {
    u64t d;
    asm("mov.b64 %0, {%1, %2};" : "=l"(d) : "f"(lo), "f"(hi));
    return d;
}
__device__ __forceinline__ float hadd2(u64t a) {   // lo + hi
    float x, y;
    asm("mov.b64 {%0, %1}, %2;" : "=f"(x), "=f"(y) : "l"(a));
    return x + y;
}
__device__ __forceinline__ float ex2a(float x) {   // 2^x, MUFU
    float y;
    asm("ex2.approx.f32 %0, %1;" : "=f"(y) : "f"(x));
    return y;
}
__device__ __forceinline__ float rcpa(float x) {   // 1/x, MUFU
    float y;
    asm("rcp.approx.f32 %0, %1;" : "=f"(y) : "f"(x));
    return y;
}

// Dense scratch: element b occupies floats [b*64, b*64+64):
//   [0:32)  renormalized user row,  [32:64) renormalized item row.
__device__ __align__(16) float g_rows[MAXB * 64];

// ── K1: gather + renorm. 8 lanes per row; one warp covers 4 rows. ──────────
__global__ __launch_bounds__(256)
void LRML_gather_kernel(const int* __restrict__ user_ids,
                        const int* __restrict__ item_ids,
                        const float* __restrict__ user_emb,
                        const float* __restrict__ item_emb,
                        int B) {
    const int t   = blockIdx.x * 256 + threadIdx.x;
    const int row = t >> 3;           // 0 .. 2B-1  (u rows then i rows)
    const int sub = t & 7;            // 16B slice within the row
    if (row >= 2 * B) return;

    const bool isU = (row < B);
    const int  el  = isU ? row : row - B;
    const int  id  = isU ? __ldg(&user_ids[el]) : __ldg(&item_ids[el]);
    const float* src = isU ? user_emb : item_emb;

    // Gather: 8 lanes cover one 128B table row.
    ulonglong2 v = __ldg((const ulonglong2*)(src + (size_t)id * 32) + sub);

    // Squared norm over the 8-lane group (3-stage butterfly).
    float n = hadd2(fma2(v.y, v.y, mul2(v.x, v.x)));
    n += __shfl_xor_sync(0xFFFFFFFFu, n, 1);
    n += __shfl_xor_sync(0xFFFFFFFFu, n, 2);
    n += __shfl_xor_sync(0xFFFFFFFFu, n, 4);

    // scale = 1/max(||e||,1) = min(rsqrt(n),1)  (n=0 -> inf -> 1, fine)
    const float sc = fminf(rsqrtf(n), 1.0f);
    const u64t sc2 = pack2(sc, sc);
    v.x = mul2(sc2, v.x);
    v.y = mul2(sc2, v.y);

    // Dense store: u-part at +0, i-part at +32 floats.
    float* dst = g_rows + (size_t)el * 64 + (isU ? 0 : 32) + sub * 4;
    *(ulonglong2*)dst = v;
}

// ── K2: compute. G=4 lanes/element; one warp covers 8 elements. ────────────
__global__ __launch_bounds__(128, 7)
void LRML_compute_kernel(const float* __restrict__ W_att,
                         const float* __restrict__ memory,
                         float* __restrict__ out,
                         int B) {
    const int tid  = threadIdx.x;
    const int lane = tid & 31;
    const int warp = tid >> 5;
    const int sub  = lane & 3;        // 8-dim slice owner (0..3)
    const int eg   = lane >> 2;       // element within warp (0..7)
    const int b = ((blockIdx.x * 4 + warp) << 3) + eg;
    const int bb = (b < B) ? b : (B - 1);

    // Dense, L2-resident loads: element block is 256B contiguous.
    const ulonglong2* ebase = (const ulonglong2*)(g_rows + (size_t)bb * 64);
    const ulonglong2 u0 = ebase[sub * 2];         // normalized user slice
    const ulonglong2 u1 = ebase[sub * 2 + 1];
    const ulonglong2 i0 = ebase[8 + sub * 2];     // normalized item slice
    const ulonglong2 i1 = ebase[8 + sub * 2 + 1];

    // Parameter slices (broadcast LDG, L1-resident). Row = 8 ulonglong2.
    const ulonglong2* Wp = (const ulonglong2*)W_att  + sub * 2;
    const ulonglong2* Mp = (const ulonglong2*)memory + sub * 2;

    // joint = ur * ir (already renormalized)
    const u64t j0 = mul2(u0.x, i0.x);
    const u64t j1 = mul2(u0.y, i0.y);
    const u64t j2 = mul2(u1.x, i1.x);
    const u64t j3 = mul2(u1.y, i1.y);

    // scores[m] partials, then merged 2-stage butterfly (10 values).
    float s[M];
    #pragma unroll
    for (int m = 0; m < M; m++) {
        const ulonglong2 w0 = __ldg(Wp + m * 8);
        const ulonglong2 w1 = __ldg(Wp + m * 8 + 1);
        s[m] = hadd2(fma2(j3, w1.y, fma2(j2, w1.x,
                     fma2(j1, w0.y, mul2(j0, w0.x)))));
    }
    #pragma unroll
    for (int o = 1; o <= 2; o <<= 1) {
        #pragma unroll
        for (int m = 0; m < M; m++)
            s[m] += __shfl_xor_sync(0xFFFFFFFFu, s[m], o);
    }

    // softmax (no max-subtract: |score| <= ~4 since both rows renormed)
    float e[M];
    #pragma unroll
    for (int m = 0; m < M; m++) e[m] = ex2a(s[m] * 1.44269504f);
    float sumA = e[0] + e[2], sumB = e[1] + e[3];
    sumA += e[4] + e[6]; sumB += e[5] + e[7];
    sumA += e[8];        sumB += e[9];
    const float inv = rcpa(sumA + sumB);

    // unnormalized rel over this lane's 8 dims; even/odd m chains.
    u64t a0 = 0ull, a1 = 0ull, a2 = 0ull, a3 = 0ull;
    u64t c0 = 0ull, c1 = 0ull, c2 = 0ull, c3 = 0ull;
    #pragma unroll
    for (int m = 0; m < M; m += 2) {
        const ulonglong2 ma0 = __ldg(Mp + m * 8);
        const ulonglong2 ma1 = __ldg(Mp + m * 8 + 1);
        const ulonglong2 mb0 = __ldg(Mp + (m + 1) * 8);
        const ulonglong2 mb1 = __ldg(Mp + (m + 1) * 8 + 1);
        const u64t pa = pack2(e[m], e[m]);
        const u64t pb = pack2(e[m + 1], e[m + 1]);
        a0 = fma2(pa, ma0.x, a0);  a1 = fma2(pa, ma0.y, a1);
        a2 = fma2(pa, ma1.x, a2);  a3 = fma2(pa, ma1.y, a3);
        c0 = fma2(pb, mb0.x, c0);  c1 = fma2(pb, mb0.y, c1);
        c2 = fma2(pb, mb1.x, c2);  c3 = fma2(pb, mb1.y, c3);
    }
    const u64t one2 = pack2(1.0f, 1.0f);
    const u64t r0 = fma2(one2, c0, a0);
    const u64t r1 = fma2(one2, c1, a1);
    const u64t r2 = fma2(one2, c2, a2);
    const u64t r3 = fma2(one2, c3, a3);

    // dist: dx = (u - i) + inv*r, packed; square; 2-SHFL group reduce.
    const u64t neg1 = pack2(-1.0f, -1.0f);
    const u64t inv2 = pack2(inv, inv);
    const u64t dx0 = fma2(inv2, r0, fma2(neg1, i0.x, u0.x));
    const u64t dx1 = fma2(inv2, r1, fma2(neg1, i0.y, u0.y));
    const u64t dx2 = fma2(inv2, r2, fma2(neg1, i1.x, u1.x));
    const u64t dx3 = fma2(inv2, r3, fma2(neg1, i1.y, u1.y));
    float d = hadd2(fma2(dx3, dx3, fma2(dx2, dx2,
                    fma2(dx1, dx1, mul2(dx0, dx0)))));
    d += __shfl_xor_sync(0xFFFFFFFFu, d, 1);
    d += __shfl_xor_sync(0xFFFFFFFFu, d, 2);

    if (sub == 0 && b < B) out[b] = -d;
}

extern "C" void kernel_launch(void* const* d_in, const int* in_sizes, int n_in,
                              void* d_out, int out_size) {
    const int*   user_ids = (const int*)  d_in[0];
    const int*   item_ids = (const int*)  d_in[1];
    const float* user_emb = (const float*)d_in[2];
    const float* item_emb = (const float*)d_in[3];
    const float* W_att    = (const float*)d_in[4];
    const float* memory   = (const float*)d_in[5];
    float* out = (float*)d_out;

    const int B = in_sizes[0];

    // K1: one thread per 16B row-slice; 2B rows * 8 slices.
    const int t1 = 2 * B * 8;
    LRML_gather_kernel<<<(t1 + 255) / 256, 256>>>(
        user_ids, item_ids, user_emb, item_emb, B);

    // K2: 32 elements per 128-thread block.
    LRML_compute_kernel<<<(B + 31) / 32, 128>>>(W_att, memory, out, B);
}

// round 15
// speedup vs baseline: 1.0748x; 1.0748x over previous
#include <cuda_runtime.h>
#include <cuda_bf16.h>
#include <math.h>

// LRML memory-network scoring — G=4 lanes/element, packed f32x2,
// barrier-free, early-norm reduction folded into the score scale.
//  0: user_ids  int32  [B]
//  1: item_ids  int32  [B]
//  2: user_emb  f32    [U, 32]
//  3: item_emb  f32    [I, 32]
//  4: W_att     f32    [10, 32]
//  5: memory    f32    [10, 32]
// Output: f32 [B] = -sum((ue + rel - ie)^2)
//
// Lane `sub` (0..3) owns dims [8*sub, 8*sub+8) as two ulonglong2
// (= four f32x2 pairs). One warp covers 8 elements; 2048 warps total.

#define M 10
#define TPB 128               // 4 warps -> 32 elements per block

typedef unsigned long long u64t;

__device__ __forceinline__ u64t fma2(u64t a, u64t b, u64t c) {
    u64t d;
    asm("fma.rn.f32x2 %0, %1, %2, %3;" : "=l"(d) : "l"(a), "l"(b), "l"(c));
    return d;
}
__device__ __forceinline__ u64t mul2(u64t a, u64t b) {
    u64t d;
    asm("mul.rn.f32x2 %0, %1, %2;" : "=l"(d) : "l"(a), "l"(b));
    return d;
}
__device__ __forceinline__ u64t pack2(float lo, float hi) {
    u64t d;
    asm("mov.b64 %0, {%1, %2};" : "=l"(d) : "f"(lo), "f"(hi));
    return d;
}
__device__ __forceinline__ float hadd2(u64t a) {   // lo + hi
    float x, y;
    asm("mov.b64 {%0, %1}, %2;" : "=f"(x), "=f"(y) : "l"(a));
    return x + y;
}
__device__ __forceinline__ float ex2a(float x) {   // 2^x, MUFU
    float y;
    asm("ex2.approx.f32 %0, %1;" : "=f"(y) : "f"(x));
    return y;
}
__device__ __forceinline__ float rcpa(float x) {   // 1/x, MUFU
    float y;
    asm("rcp.approx.f32 %0, %1;" : "=f"(y) : "f"(x));
    return y;
}

__global__ __launch_bounds__(TPB, 7)
void LRML_90804198572513_kernel(const int* __restrict__ user_ids,
                                const int* __restrict__ item_ids,
                                const float* __restrict__ user_emb,
                                const float* __restrict__ item_emb,
                                const float* __restrict__ W_att,
                                const float* __restrict__ memory,
                                float* __restrict__ out,
                                int B) {
    const int tid  = threadIdx.x;
    const int lane = tid & 31;
    const int warp = tid >> 5;
    const int sub  = lane & 3;        // 8-dim slice owner (0..3)
    const int eg   = lane >> 2;       // element within warp (0..7)
    const int b = ((blockIdx.x * (TPB / 32) + warp) << 3) + eg;
    const int bb = (b < B) ? b : (B - 1);

    // 1) ids first (dependent DRAM/L2 load)
    const int uid = __ldg(&user_ids[bb]);
    const int iid = __ldg(&item_ids[bb]);

    // 2) row gathers: lanes 0..3 of a group cover one full 128B row.
    const ulonglong2* ubase = (const ulonglong2*)(user_emb + (size_t)uid * 32) + sub * 2;
    const ulonglong2* ibase = (const ulonglong2*)(item_emb + (size_t)iid * 32) + sub * 2;
    const ulonglong2 u0 = __ldg(ubase);
    const ulonglong2 u1 = __ldg(ubase + 1);
    const ulonglong2 i0 = __ldg(ibase);
    const ulonglong2 i1 = __ldg(ibase + 1);

    // Parameter slices (broadcast LDG, L1-resident). Row = 8 ulonglong2.
    const ulonglong2* Wp = (const ulonglong2*)W_att  + sub * 2;
    const ulonglong2* Mp = (const ulonglong2*)memory + sub * 2;

    // 3) EARLY norm reduction: packed partials, tiny 2-value butterfly.
    const u64t nup = fma2(u1.y, u1.y, fma2(u1.x, u1.x,
                     fma2(u0.y, u0.y, mul2(u0.x, u0.x))));
    const u64t nip = fma2(i1.y, i1.y, fma2(i1.x, i1.x,
                     fma2(i0.y, i0.y, mul2(i0.x, i0.x))));
    float nu = hadd2(nup), ni = hadd2(nip);
    nu += __shfl_xor_sync(0xFFFFFFFFu, nu, 1);
    ni += __shfl_xor_sync(0xFFFFFFFFu, ni, 1);
    nu += __shfl_xor_sync(0xFFFFFFFFu, nu, 2);
    ni += __shfl_xor_sync(0xFFFFFFFFu, ni, 2);

    // scale = 1/max(||e||,1) = min(rsqrt(n),1)   (n=0 -> inf -> 1, fine)
    const float su  = fminf(rsqrtf(nu), 1.0f);
    const float si  = fminf(rsqrtf(ni), 1.0f);
    const float sjE = su * si * 1.44269504f;      // log2(e) folded in
    const u64t sjE2 = pack2(sjE, sjE);

    // 4) pre-scaled joint: scores come out already multiplied by sjE.
    const u64t j0 = mul2(sjE2, mul2(u0.x, i0.x));
    const u64t j1 = mul2(sjE2, mul2(u0.y, i0.y));
    const u64t j2 = mul2(sjE2, mul2(u1.x, i1.x));
    const u64t j3 = mul2(sjE2, mul2(u1.y, i1.y));

    // 5) score partials + merged 2-stage butterfly (10 values).
    float s[M];
    #pragma unroll
    for (int m = 0; m < M; m++) {
        const ulonglong2 w0 = __ldg(Wp + m * 8);
        const ulonglong2 w1 = __ldg(Wp + m * 8 + 1);
        s[m] = hadd2(fma2(j3, w1.y, fma2(j2, w1.x,
                     fma2(j1, w0.y, mul2(j0, w0.x)))));
    }
    #pragma unroll
    for (int o = 1; o <= 2; o <<= 1) {
        #pragma unroll
        for (int m = 0; m < M; m++)
            s[m] += __shfl_xor_sync(0xFFFFFFFFu, s[m], o);
    }

    // 6) softmax numerators directly (no max-subtract: |score| <~ 4).
    float e[M];
    #pragma unroll
    for (int m = 0; m < M; m++) e[m] = ex2a(s[m]);
    float sumA = e[0] + e[2], sumB = e[1] + e[3];
    sumA += e[4] + e[6]; sumB += e[5] + e[7];
    sumA += e[8];        sumB += e[9];
    const float inv = rcpa(sumA + sumB);

    // 7) unnormalized rel over this lane's 8 dims; even/odd m chains.
    u64t a0 = 0ull, a1 = 0ull, a2 = 0ull, a3 = 0ull;   // even m
    u64t c0 = 0ull, c1 = 0ull, c2 = 0ull, c3 = 0ull;   // odd  m
    #pragma unroll
    for (int m = 0; m < M; m += 2) {
        const ulonglong2 ma0 = __ldg(Mp + m * 8);
        const ulonglong2 ma1 = __ldg(Mp + m * 8 + 1);
        const ulonglong2 mb0 = __ldg(Mp + (m + 1) * 8);
        const ulonglong2 mb1 = __ldg(Mp + (m + 1) * 8 + 1);
        const u64t pa = pack2(e[m], e[m]);
        const u64t pb = pack2(e[m + 1], e[m + 1]);
        a0 = fma2(pa, ma0.x, a0);  a1 = fma2(pa, ma0.y, a1);
        a2 = fma2(pa, ma1.x, a2);  a3 = fma2(pa, ma1.y, a3);
        c0 = fma2(pb, mb0.x, c0);  c1 = fma2(pb, mb0.y, c1);
        c2 = fma2(pb, mb1.x, c2);  c3 = fma2(pb, mb1.y, c3);
    }
    const u64t one2 = pack2(1.0f, 1.0f);
    const u64t r0 = fma2(one2, c0, a0);
    const u64t r1 = fma2(one2, c1, a1);
    const u64t r2 = fma2(one2, c2, a2);
    const u64t r3 = fma2(one2, c3, a3);

    // 8) dist: dx = su*u + inv*r - si*i (packed), square, 2-SHFL reduce.
    const u64t su2  = pack2(su, su);
    const u64t nsi2 = pack2(-si, -si);
    const u64t inv2 = pack2(inv, inv);
    const u64t dx0 = fma2(su2, u0.x, fma2(nsi2, i0.x, mul2(inv2, r0)));
    const u64t dx1 = fma2(su2, u0.y, fma2(nsi2, i0.y, mul2(inv2, r1)));
    const u64t dx2 = fma2(su2, u1.x, fma2(nsi2, i1.x, mul2(inv2, r2)));
    const u64t dx3 = fma2(su2, u1.y, fma2(nsi2, i1.y, mul2(inv2, r3)));
    float d = hadd2(fma2(dx3, dx3, fma2(dx2, dx2,
                    fma2(dx1, dx1, mul2(dx0, dx0)))));
    d += __shfl_xor_sync(0xFFFFFFFFu, d, 1);
    d += __shfl_xor_sync(0xFFFFFFFFu, d, 2);

    if (sub == 0 && b < B) out[b] = -d;
}

extern "C" void kernel_launch(void* const* d_in, const int* in_sizes, int n_in,
                              void* d_out, int out_size) {
    const int*   user_ids = (const int*)  d_in[0];
    const int*   item_ids = (const int*)  d_in[1];
    const float* user_emb = (const float*)d_in[2];
    const float* item_emb = (const float*)d_in[3];
    const float* W_att    = (const float*)d_in[4];
    const float* memory   = (const float*)d_in[5];
    float* out = (float*)d_out;

    const int B = in_sizes[0];
    const int elems_per_block = (TPB / 32) * 8;  // 32
    const int grid = (B + elems_per_block - 1) / elems_per_block;
    LRML_90804198572513_kernel<<<grid, TPB>>>(
        user_ids, item_ids, user_emb, item_emb, W_att, memory, out, B);
}

// round 16
// speedup vs baseline: 1.3000x; 1.2095x over previous
#include <cuda_runtime.h>
#include <cuda_bf16.h>
#include <math.h>

// LRML memory-network scoring — G=4 lanes/element, packed f32x2,
// barrier-free; R12 structure + register prefetch of both parameter
// matrices so their first-touch latency hides under the gather chain.
//  0: user_ids  int32  [B]
//  1: item_ids  int32  [B]
//  2: user_emb  f32    [U, 32]
//  3: item_emb  f32    [I, 32]
//  4: W_att     f32    [10, 32]
//  5: memory    f32    [10, 32]
// Output: f32 [B] = -sum((ue + rel - ie)^2)
//
// Lane `sub` (0..3) owns dims [8*sub, 8*sub+8) as two ulonglong2
// (= four f32x2 pairs). One warp covers 8 elements; 2048 warps total.

#define M 10
#define TPB 128               // 4 warps -> 32 elements per block

typedef unsigned long long u64t;

__device__ __forceinline__ u64t fma2(u64t a, u64t b, u64t c) {
    u64t d;
    asm("fma.rn.f32x2 %0, %1, %2, %3;" : "=l"(d) : "l"(a), "l"(b), "l"(c));
    return d;
}
__device__ __forceinline__ u64t mul2(u64t a, u64t b) {
    u64t d;
    asm("mul.rn.f32x2 %0, %1, %2;" : "=l"(d) : "l"(a), "l"(b));
    return d;
}
__device__ __forceinline__ u64t pack2(float lo, float hi) {
    u64t d;
    asm("mov.b64 %0, {%1, %2};" : "=l"(d) : "f"(lo), "f"(hi));
    return d;
}
__device__ __forceinline__ float hadd2(u64t a) {   // lo + hi
    float x, y;
    asm("mov.b64 {%0, %1}, %2;" : "=f"(x), "=f"(y) : "l"(a));
    return x + y;
}
__device__ __forceinline__ float ex2a(float x) {   // 2^x, MUFU
    float y;
    asm("ex2.approx.f32 %0, %1;" : "=f"(y) : "f"(x));
    return y;
}
__device__ __forceinline__ float rcpa(float x) {   // 1/x, MUFU
    float y;
    asm("rcp.approx.f32 %0, %1;" : "=f"(y) : "f"(x));
    return y;
}

__global__ __launch_bounds__(TPB, 4)
void LRML_90804198572513_kernel(const int* __restrict__ user_ids,
                                const int* __restrict__ item_ids,
                                const float* __restrict__ user_emb,
                                const float* __restrict__ item_emb,
                                const float* __restrict__ W_att,
                                const float* __restrict__ memory,
                                float* __restrict__ out,
                                int B) {
    const int tid  = threadIdx.x;
    const int lane = tid & 31;
    const int warp = tid >> 5;
    const int sub  = lane & 3;        // 8-dim slice owner (0..3)
    const int eg   = lane >> 2;       // element within warp (0..7)
    const int b = ((blockIdx.x * (TPB / 32) + warp) << 3) + eg;
    if (b >= B) return;

    // 1) ids (start of the dependent DRAM chain)
    const int uid = __ldg(&user_ids[b]);
    const int iid = __ldg(&item_ids[b]);

    // 2) PREFETCH all W slices into registers — independent of ids/rows,
    //    their L2 first-touch latency rides under the gather chain.
    //    Row stride = 32 floats = 8 ulonglong2; lane takes sub*2, sub*2+1.
    const ulonglong2* Wp = (const ulonglong2*)W_att  + sub * 2;
    const ulonglong2* Mp = (const ulonglong2*)memory + sub * 2;
    ulonglong2 w0r[M], w1r[M];
    #pragma unroll
    for (int m = 0; m < M; m++) {
        w0r[m] = __ldg(Wp + m * 8);
        w1r[m] = __ldg(Wp + m * 8 + 1);
    }

    // 3) row gathers: lanes 0..3 of a group cover one full 128B row.
    const ulonglong2* ubase = (const ulonglong2*)(user_emb + (size_t)uid * 32) + sub * 2;
    const ulonglong2* ibase = (const ulonglong2*)(item_emb + (size_t)iid * 32) + sub * 2;
    const ulonglong2 u0 = __ldg(ubase);
    const ulonglong2 u1 = __ldg(ubase + 1);
    const ulonglong2 i0 = __ldg(ibase);
    const ulonglong2 i1 = __ldg(ibase + 1);

    // 4) per-lane partials: norms + unscaled scores (packed math)
    float red[2 + M];
    red[0] = hadd2(fma2(u1.y, u1.y, fma2(u1.x, u1.x,
                   fma2(u0.y, u0.y, mul2(u0.x, u0.x)))));
    red[1] = hadd2(fma2(i1.y, i1.y, fma2(i1.x, i1.x,
                   fma2(i0.y, i0.y, mul2(i0.x, i0.x)))));

    const u64t j0 = mul2(u0.x, i0.x);   // unscaled joint slice (4 f32x2)
    const u64t j1 = mul2(u0.y, i0.y);
    const u64t j2 = mul2(u1.x, i1.x);
    const u64t j3 = mul2(u1.y, i1.y);
    #pragma unroll
    for (int m = 0; m < M; m++) {
        red[2 + m] = hadd2(fma2(j3, w1r[m].y, fma2(j2, w1r[m].x,
                           fma2(j1, w0r[m].y, mul2(j0, w0r[m].x)))));
    }

    // 5) PREFETCH memory slices now — latency hides under butterfly+softmax.
    ulonglong2 m0r[M], m1r[M];
    #pragma unroll
    for (int m = 0; m < M; m++) {
        m0r[m] = __ldg(Mp + m * 8);
        m1r[m] = __ldg(Mp + m * 8 + 1);
    }

    // 6) merged 2-stage butterfly over the 4-lane group (12 values, pipelined)
    #pragma unroll
    for (int o = 1; o <= 2; o <<= 1) {
        #pragma unroll
        for (int k = 0; k < 2 + M; k++)
            red[k] += __shfl_xor_sync(0xFFFFFFFFu, red[k], o);
    }

    // 7) scales; fold renorm product and log2(e) into one exp multiplier.
    //    scale = 1/max(||e||,1) = min(rsqrt(n),1)   (n=0 -> inf -> 1, fine)
    const float su  = fminf(rsqrtf(red[0]), 1.0f);
    const float si  = fminf(rsqrtf(red[1]), 1.0f);
    const float sjE = su * si * 1.44269504f;

    // 8) softmax numerators (no max-subtract: |score| <~ 4, fp32-safe)
    float e[M];
    #pragma unroll
    for (int m = 0; m < M; m++) e[m] = ex2a(red[2 + m] * sjE);
    float sumA = e[0] + e[2], sumB = e[1] + e[3];
    sumA += e[4] + e[6]; sumB += e[5] + e[7];
    sumA += e[8];        sumB += e[9];
    const float inv = rcpa(sumA + sumB);

    // 9) unnormalized rel over this lane's 8 dims; even/odd m chains,
    //    all memory slices already in registers.
    u64t a0 = 0ull, a1 = 0ull, a2 = 0ull, a3 = 0ull;   // even m
    u64t c0 = 0ull, c1 = 0ull, c2 = 0ull, c3 = 0ull;   // odd  m
    #pragma unroll
    for (int m = 0; m < M; m += 2) {
        const u64t pa = pack2(e[m], e[m]);
        const u64t pb = pack2(e[m + 1], e[m + 1]);
        a0 = fma2(pa, m0r[m].x, a0);      a1 = fma2(pa, m0r[m].y, a1);
        a2 = fma2(pa, m1r[m].x, a2);      a3 = fma2(pa, m1r[m].y, a3);
        c0 = fma2(pb, m0r[m + 1].x, c0);  c1 = fma2(pb, m0r[m + 1].y, c1);
        c2 = fma2(pb, m1r[m + 1].x, c2);  c3 = fma2(pb, m1r[m + 1].y, c3);
    }
    const u64t one2 = pack2(1.0f, 1.0f);
    const u64t r0 = fma2(one2, c0, a0);
    const u64t r1 = fma2(one2, c1, a1);
    const u64t r2 = fma2(one2, c2, a2);
    const u64t r3 = fma2(one2, c3, a3);

    // 10) dist: dx = su*u + inv*r - si*i (packed), square, 2-SHFL reduce.
    const u64t su2  = pack2(su, su);
    const u64t nsi2 = pack2(-si, -si);
    const u64t inv2 = pack2(inv, inv);
    const u64t dx0 = fma2(su2, u0.x, fma2(nsi2, i0.x, mul2(inv2, r0)));
    const u64t dx1 = fma2(su2, u0.y, fma2(nsi2, i0.y, mul2(inv2, r1)));
    const u64t dx2 = fma2(su2, u1.x, fma2(nsi2, i1.x, mul2(inv2, r2)));
    const u64t dx3 = fma2(su2, u1.y, fma2(nsi2, i1.y, mul2(inv2, r3)));
    float d = hadd2(fma2(dx3, dx3, fma2(dx2, dx2,
                    fma2(dx1, dx1, mul2(dx0, dx0)))));
    d += __shfl_xor_sync(0xFFFFFFFFu, d, 1);
    d += __shfl_xor_sync(0xFFFFFFFFu, d, 2);

    if (sub == 0) out[b] = -d;
}

extern "C" void kernel_launch(void* const* d_in, const int* in_sizes, int n_in,
                              void* d_out, int out_size) {
    const int*   user_ids = (const int*)  d_in[0];
    const int*   item_ids = (const int*)  d_in[1];
    const float* user_emb = (const float*)d_in[2];
    const float* item_emb = (const float*)d_in[3];
    const float* W_att    = (const float*)d_in[4];
    const float* memory   = (const float*)d_in[5];
    float* out = (float*)d_out;

    const int B = in_sizes[0];
    const int elems_per_block = (TPB / 32) * 8;  // 32
    const int grid = (B + elems_per_block - 1) / elems_per_block;
    LRML_90804198572513_kernel<<<grid, TPB>>>(
        user_ids, item_ids, user_emb, item_emb, W_att, memory, out, B);
}